// round 15
// baseline (speedup 1.0000x reference)
#include <cuda_runtime.h>
#include <cuda_fp16.h>
#include <cstdint>
#include <cstddef>

#define B_   8
#define C_   512
#define L_   8192
#define NW   6
#define WELEM (512*512*3)
#define ACT  (B_*C_*L_)   // 33554432

// ---------------- scratch (device globals; no allocs allowed) ----------------
__device__ __align__(256) double  g_partial[NW*96];
__device__ __align__(256) float   g_scales[NW];
__device__ __align__(256) __half  g_wq[NW*WELEM];   // per weight: [k][o][i] ternary fp16
__device__ __align__(256) __half  g_xt0[ACT];       // fp16 activations [b][L][C] ping
__device__ __align__(256) __half  g_xt1[ACT];       // pong
__device__ __align__(256) __half  g_yt[ACT];        // branch intermediate [b][L][C]
__device__ __align__(256) float   g_xf0[ACT];       // fp32 residual [b][C][L] ping
__device__ __align__(256) float   g_xf1[ACT];       // pong

struct WPtrs { const float* p[NW]; };

__device__ __forceinline__ uint32_t smem_u32(const void* p) {
    uint32_t a;
    asm("{ .reg .u64 t; cvta.to.shared.u64 t, %1; cvt.u32.u64 %0, t; }"
        : "=r"(a) : "l"(p));
    return a;
}
__device__ __forceinline__ void cpa16(uint32_t dst, const void* src, uint32_t ssize) {
    asm volatile("cp.async.cg.shared.global [%0], [%1], 16, %2;"
                 :: "r"(dst), "l"(src), "r"(ssize) : "memory");
}
#define LDSM_X4(r0,r1,r2,r3,a) \
    asm volatile("ldmatrix.sync.aligned.m8n8.x4.shared.b16 {%0,%1,%2,%3}, [%4];" \
                 : "=r"(r0),"=r"(r1),"=r"(r2),"=r"(r3) : "r"(a))
#define MMA16816(acc, A0,A1,A2,A3, B0,B1) \
    asm volatile( \
        "mma.sync.aligned.m16n8k16.row.col.f32.f16.f16.f32 " \
        "{%0,%1,%2,%3}, {%4,%5,%6,%7}, {%8,%9}, {%0,%1,%2,%3};\n" \
        : "+f"((acc)[0]), "+f"((acc)[1]), "+f"((acc)[2]), "+f"((acc)[3]) \
        : "r"(A0), "r"(A1), "r"(A2), "r"(A3), "r"(B0), "r"(B1))

// ---------------- pass 1: deterministic |w| partial sums (double) ------------
__global__ void wabs_kernel(WPtrs wp) {
    int e = blockIdx.y;
    int chunk = blockIdx.x;                 // 96 chunks of 8192
    const float* w = wp.p[e] + chunk * 8192;
    double s = 0.0;
    for (int i = threadIdx.x; i < 8192; i += 256) s += (double)fabsf(w[i]);
    __shared__ double sm[256];
    sm[threadIdx.x] = s;
    __syncthreads();
    for (int off = 128; off > 0; off >>= 1) {
        if (threadIdx.x < off) sm[threadIdx.x] += sm[threadIdx.x + off];
        __syncthreads();
    }
    if (threadIdx.x == 0) g_partial[e*96 + chunk] = sm[0];
}

// ---------------- pass 2: finalize scales ------------------------------------
__global__ void finalize_kernel() {
    int e = threadIdx.x;
    if (e < NW) {
        double s = 0.0;
        for (int i = 0; i < 96; i++) s += g_partial[e*96 + i];
        g_scales[e] = (float)(s / (double)WELEM) + 1e-5f;
    }
}

// ---------------- pass 3: ternary quantize + rearrange [o][i][k]->[k][o][i] --
__global__ void quant_kernel(WPtrs wp) {
    int idx = blockIdx.x * 256 + threadIdx.x;
    if (idx >= NW * WELEM) return;
    int e = idx / WELEM;
    int r = idx - e * WELEM;
    int o = r / 1536;
    int rem = r - o * 1536;
    int i = rem / 3;
    int k = rem - i * 3;
    float sc = g_scales[e];
    float t = rintf(wp.p[e][r] / sc);       // round-half-even, matches jnp.round
    t = fminf(1.f, fmaxf(-1.f, t));
    g_wq[(size_t)e * WELEM + ((size_t)(k * C_ + o) * C_ + i)] = __float2half_rn(t);
}

// ---------------- transpose x[b][C][L] fp32 -> xT[b][L][C] fp16 ---------------
// 32 l x 64 c tiles; half2 stores give 128B/warp write transactions.
__global__ void tr_kernel(const float* __restrict__ x) {
    __shared__ __half t[64][33];   // [c][l]
    int b  = blockIdx.z;
    int l0 = blockIdx.x * 32, c0 = blockIdx.y * 64;
    int tx = threadIdx.x, ty = threadIdx.y;   // 32 x 8
    const float* xp = x + ((size_t)b * C_ + c0) * L_ + l0;
#pragma unroll
    for (int j = 0; j < 64; j += 8)
        t[ty + j][tx] = __float2half_rn(xp[(size_t)(ty + j) * L_ + tx]);
    __syncthreads();
    __half* xo = g_xt0 + ((size_t)b * L_ + l0) * C_ + c0;
#pragma unroll
    for (int r = 0; r < 4; r++) {
        int l = ty * 4 + r;                   // uniform per warp
        __half2 v;
        v.x = t[2 * tx    ][l];
        v.y = t[2 * tx + 1][l];
        *(__half2*)(xo + (size_t)l * C_ + 2 * tx) = v;
    }
}

// ---------------- fused conv (mma.sync fp16, ldmatrix + cp.async 2-buf) -------
// CTA tile: 128 o x 256 n (W fill amortized over 2x the n). 1 CTA/SM (128 acc).
// K = 3 taps x 512 ic in 16 chunks of 32. Rows padded to 40 halves (80B).
//   Ws: [buf][3][128][40]  at offset buf*30720           (2 x 30720 B)
//   Xs: [buf][272][40]     at offset 61440 + buf*21760   (2 x 21760 B)
// Total 104960 B dynamic. Epilogue reuses smem as 256n x 136o fp16 staging
// tile (69632 B) for fully-coalesced [L][C] fp16 stores.
// B operand: Xs stored [n][k] (k contiguous) -> NON-trans ldmatrix gives the
// exact m16n8k16 B fragment (thread i: Xs[n=i>>2][k=(i&3)*2 .. +1]).
// MODE 0: out_h[L][C] = fp16(leaky(scale*acc + bias))
// MODE 1: r = prev_f + scale*acc + bias -> out_f [C][L] fp32; opt out_h [L][C]
#define CONV_SMEM 104960
template<int D, int MODE>
__global__ __launch_bounds__(256, 1)
void conv_kernel(const __half* __restrict__ xin,        // [b][L][C] fp16
                 const __half* __restrict__ wq,         // [3][512][512] ternary fp16
                 const float* __restrict__ scale_p,
                 const float* __restrict__ bias,
                 const float* __restrict__ prev_f,
                 float* __restrict__ out_f,
                 __half* __restrict__ out_h,
                 int write_h)
{
    extern __shared__ char dsm[];
    const uint32_t sb = smem_u32(dsm);

    const int n0 = blockIdx.x * 256;
    const int o0 = blockIdx.y * 128;
    const int b  = blockIdx.z;
    const int tid  = threadIdx.x;
    const int lane = tid & 31;
    const int wid  = tid >> 5;
    const int oW = (wid & 3) * 32;    // warp o-offset (4 warps across o)
    const int nW = (wid >> 2) * 128;  // warp n-offset (2 warps across n)

    float acc[2][16][4];
#pragma unroll
    for (int a = 0; a < 2; a++)
#pragma unroll
        for (int c = 0; c < 16; c++)
#pragma unroll
            for (int j = 0; j < 4; j++) acc[a][c][j] = 0.f;

    const size_t bL = (size_t)b * L_;

    // stage fill: 1536 W chunks (3*128 rows x 4x16B) + 1088 X chunks (272 x 4x16B)
    auto fill = [&](int s, int buf) {
        int ic = s * 32;
        uint32_t wbase = sb + buf * 30720;
        uint32_t xbase = sb + 61440 + buf * 21760;
#pragma unroll
        for (int i = 0; i < 11; i++) {
            int c = tid + i * 256;
            if (c < 1536) {                       // weights
                int row = c >> 2, q = c & 3;
                int t = row >> 7, o = row & 127;
                const __half* src = wq + ((size_t)(t * C_ + o0 + o)) * C_ + ic + q * 8;
                cpa16(wbase + (uint32_t)(((t * 128 + o) * 40 + q * 8) * 2), src, 16);
            } else if (c < 2624) {                // activations
                int c2 = c - 1536;
                int r = c2 >> 2, q = c2 & 3;
                int l = n0 - 8 + r;
                int lc = l < 0 ? 0 : (l >= L_ ? L_ - 1 : l);
                uint32_t sz = (l >= 0 && l < L_) ? 16u : 0u;
                const __half* src = xin + (bL + lc) * C_ + ic + q * 8;
                cpa16(xbase + (uint32_t)((r * 40 + q * 8) * 2), src, sz);
            }
        }
        asm volatile("cp.async.commit_group;" ::: "memory");
    };

    // per-lane ldmatrix address components
    const uint32_t aRow  = lane & 15;                 // A: row within 16
    const uint32_t aColH = (lane >> 4) * 8;           // A: k-half select
    const uint32_t bR    = lane & 7;                  // B: n-row within 8x8 tile
    const uint32_t bNH   = ((lane >> 4) & 1) * 8;     // B: n-tile select (matrices 2,3)
    const uint32_t bKH   = ((lane >> 3) & 1) * 8;     // B: k-half select (matrices 1,3)

    fill(0, 0);
    for (int s = 0; s < 16; s++) {
        const int buf = s & 1;
        asm volatile("cp.async.wait_group 0;" ::: "memory");
        __syncthreads();
        if (s + 1 < 16) fill(s + 1, buf ^ 1);

        const uint32_t wbase = sb + buf * 30720;
        const uint32_t xbase = sb + 61440 + buf * 21760;

#pragma unroll
        for (int t = 0; t < 3; t++) {
            const int shift = (8 - D) + t * D;
            const uint32_t nrow = nW + bNH + bR + shift;
#pragma unroll
            for (int kg = 0; kg < 2; kg++) {
                uint32_t a0,a1,a2,a3, a4,a5,a6,a7;
                uint32_t aa = wbase + ((t * 128 + oW + aRow) * 40 + kg * 16 + aColH) * 2;
                LDSM_X4(a0,a1,a2,a3, aa);
                LDSM_X4(a4,a5,a6,a7, aa + 16 * 80);
#pragma unroll
                for (int nia = 0; nia < 8; nia++) {
                    uint32_t b0,b1,b2,b3;
                    uint32_t ba = xbase + ((nrow + nia * 16) * 40 + kg * 16 + bKH) * 2;
                    LDSM_X4(b0,b1,b2,b3, ba);     // non-trans: [n][k] rows ARE B frags
                    MMA16816(acc[0][2*nia    ], a0,a1,a2,a3, b0,b1);
                    MMA16816(acc[0][2*nia + 1], a0,a1,a2,a3, b2,b3);
                    MMA16816(acc[1][2*nia    ], a4,a5,a6,a7, b0,b1);
                    MMA16816(acc[1][2*nia + 1], a4,a5,a6,a7, b2,b3);
                }
            }
        }
    }

    const float scale = *scale_p;
    const bool stage_h = (MODE == 0) || (write_h != 0);
    __half* ho = (__half*)dsm;               // 256 rows x 136 halves (272 B/row)

    if (stage_h) __syncthreads();            // all K-loop smem readers done

#pragma unroll
    for (int mi = 0; mi < 2; mi++) {
#pragma unroll
        for (int half = 0; half < 2; half++) {
            int ol = oW + mi*16 + (lane >> 2) + half*8;   // 0..127
            int o  = o0 + ol;
            float bv = bias[o];
#pragma unroll
            for (int ni = 0; ni < 16; ni++) {
                int cl = nW + ni*8 + (lane & 3)*2;        // 0..255
                float v0 = acc[mi][ni][half*2 + 0] * scale + bv;
                float v1 = acc[mi][ni][half*2 + 1] * scale + bv;
                if (MODE == 0) {
                    v0 = v0 >= 0.f ? v0 : 0.1f * v0;
                    v1 = v1 >= 0.f ? v1 : 0.1f * v1;
                    ho[(cl    ) * 136 + ol] = __float2half_rn(v0);
                    ho[(cl + 1) * 136 + ol] = __float2half_rn(v1);
                } else {
                    size_t gi = ((size_t)b * C_ + o) * L_ + n0 + cl;
                    float2 pv = *((const float2*)(prev_f + gi));
                    float r0 = pv.x + v0, r1 = pv.y + v1;
                    *((float2*)(out_f + gi)) = make_float2(r0, r1);
                    if (write_h) {
                        ho[(cl    ) * 136 + ol] = __float2half_rn(r0);
                        ho[(cl + 1) * 136 + ol] = __float2half_rn(r1);
                    }
                }
            }
        }
    }

    if (stage_h) {
        __syncthreads();
        // cooperative coalesced write: 256 rows x 256 B
#pragma unroll
        for (int i = 0; i < 16; i++) {
            int idx = i * 256 + tid;          // 0..4095
            int row = idx >> 4, seg = idx & 15;
            uint4 v = *(const uint4*)(dsm + row * 272 + seg * 16);
            *(uint4*)(out_h + (bL + n0 + row) * C_ + o0 + seg * 8) = v;
        }
    }
}

// ---------------- launch ------------------------------------------------------
extern "C" void kernel_launch(void* const* d_in, const int* in_sizes, int n_in,
                              void* d_out, int out_size)
{
    (void)in_sizes; (void)n_in; (void)out_size;
    const float* x = (const float*)d_in[0];
    WPtrs wp;
    const float* biasA[3];
    const float* biasB[3];
    for (int br = 0; br < 3; br++) {
        wp.p[2*br + 0] = (const float*)d_in[1 + 4*br];   // wA
        biasA[br]      = (const float*)d_in[2 + 4*br];   // bA
        wp.p[2*br + 1] = (const float*)d_in[3 + 4*br];   // wB
        biasB[br]      = (const float*)d_in[4 + 4*br];   // bB
    }

    void *p_wq, *p_x0, *p_x1, *p_y, *p_f0, *p_f1, *p_sc;
    cudaGetSymbolAddress(&p_wq, g_wq);
    cudaGetSymbolAddress(&p_x0, g_xt0);
    cudaGetSymbolAddress(&p_x1, g_xt1);
    cudaGetSymbolAddress(&p_y,  g_yt);
    cudaGetSymbolAddress(&p_f0, g_xf0);
    cudaGetSymbolAddress(&p_f1, g_xf1);
    cudaGetSymbolAddress(&p_sc, g_scales);
    __half* wq  = (__half*)p_wq;
    __half* xt0 = (__half*)p_x0;
    __half* xt1 = (__half*)p_x1;
    __half* yt  = (__half*)p_y;
    float* xf0 = (float*)p_f0;
    float* xf1 = (float*)p_f1;
    float* scales = (float*)p_sc;

    cudaFuncSetAttribute(conv_kernel<1,0>, cudaFuncAttributeMaxDynamicSharedMemorySize, CONV_SMEM);
    cudaFuncSetAttribute(conv_kernel<1,1>, cudaFuncAttributeMaxDynamicSharedMemorySize, CONV_SMEM);
    cudaFuncSetAttribute(conv_kernel<3,0>, cudaFuncAttributeMaxDynamicSharedMemorySize, CONV_SMEM);
    cudaFuncSetAttribute(conv_kernel<5,0>, cudaFuncAttributeMaxDynamicSharedMemorySize, CONV_SMEM);

    dim3 rg(96, NW);
    wabs_kernel<<<rg, 256>>>(wp);
    finalize_kernel<<<1, 32>>>();
    quant_kernel<<<(NW * WELEM + 255) / 256, 256>>>(wp);
    dim3 tg(L_ / 32, C_ / 64, B_);
    tr_kernel<<<tg, dim3(32, 8)>>>(x);

    dim3 cg(L_ / 256, C_ / 128, B_);   // 32 x 4 x 8 = 1024 CTAs
    // branch 0: dilation 1
    conv_kernel<1, 0><<<cg, 256, CONV_SMEM>>>(xt0, wq + 0*(size_t)WELEM, scales + 0, biasA[0],
                                              nullptr, nullptr, yt, 0);
    conv_kernel<1, 1><<<cg, 256, CONV_SMEM>>>(yt,  wq + 1*(size_t)WELEM, scales + 1, biasB[0],
                                              x, xf0, xt1, 1);
    // branch 1: dilation 3
    conv_kernel<3, 0><<<cg, 256, CONV_SMEM>>>(xt1, wq + 2*(size_t)WELEM, scales + 2, biasA[1],
                                              nullptr, nullptr, yt, 0);
    conv_kernel<1, 1><<<cg, 256, CONV_SMEM>>>(yt,  wq + 3*(size_t)WELEM, scales + 3, biasB[1],
                                              xf0, xf1, xt0, 1);
    // branch 2: dilation 5
    conv_kernel<5, 0><<<cg, 256, CONV_SMEM>>>(xt0, wq + 4*(size_t)WELEM, scales + 4, biasA[2],
                                              nullptr, nullptr, yt, 0);
    conv_kernel<1, 1><<<cg, 256, CONV_SMEM>>>(yt,  wq + 5*(size_t)WELEM, scales + 5, biasB[2],
                                              xf1, (float*)d_out, nullptr, 0);
}

// round 16
// speedup vs baseline: 1.0130x; 1.0130x over previous
#include <cuda_runtime.h>
#include <cuda_fp16.h>
#include <cstdint>
#include <cstddef>

#define B_   8
#define C_   512
#define L_   8192
#define NW   6
#define WELEM (512*512*3)
#define ACT  (B_*C_*L_)   // 33554432

// ---------------- scratch (device globals; no allocs allowed) ----------------
__device__ __align__(256) double  g_partial[NW*96];
__device__ __align__(256) float   g_scales[NW];
__device__ __align__(256) __half  g_wq[NW*WELEM];   // per weight: [k][o][i] ternary fp16
__device__ __align__(256) __half  g_xt0[ACT];       // fp16 activations [b][L][C] ping
__device__ __align__(256) __half  g_xt1[ACT];       // pong
__device__ __align__(256) __half  g_yt[ACT];        // branch intermediate [b][L][C]
__device__ __align__(256) float   g_xf0[ACT];       // fp32 residual [b][C][L] ping
__device__ __align__(256) float   g_xf1[ACT];       // pong

struct WPtrs { const float* p[NW]; };

__device__ __forceinline__ uint32_t smem_u32(const void* p) {
    uint32_t a;
    asm("{ .reg .u64 t; cvta.to.shared.u64 t, %1; cvt.u32.u64 %0, t; }"
        : "=r"(a) : "l"(p));
    return a;
}
__device__ __forceinline__ void cpa16(uint32_t dst, const void* src, uint32_t ssize) {
    asm volatile("cp.async.cg.shared.global [%0], [%1], 16, %2;"
                 :: "r"(dst), "l"(src), "r"(ssize) : "memory");
}
#define LDSM_X4(r0,r1,r2,r3,a) \
    asm volatile("ldmatrix.sync.aligned.m8n8.x4.shared.b16 {%0,%1,%2,%3}, [%4];" \
                 : "=r"(r0),"=r"(r1),"=r"(r2),"=r"(r3) : "r"(a))
#define MMA16816(acc, A0,A1,A2,A3, B0,B1) \
    asm volatile( \
        "mma.sync.aligned.m16n8k16.row.col.f32.f16.f16.f32 " \
        "{%0,%1,%2,%3}, {%4,%5,%6,%7}, {%8,%9}, {%0,%1,%2,%3};\n" \
        : "+f"((acc)[0]), "+f"((acc)[1]), "+f"((acc)[2]), "+f"((acc)[3]) \
        : "r"(A0), "r"(A1), "r"(A2), "r"(A3), "r"(B0), "r"(B1))

// ---------------- pass 1: deterministic |w| partial sums (double) ------------
__global__ void wabs_kernel(WPtrs wp) {
    int e = blockIdx.y;
    int chunk = blockIdx.x;                 // 96 chunks of 8192
    const float* w = wp.p[e] + chunk * 8192;
    double s = 0.0;
    for (int i = threadIdx.x; i < 8192; i += 256) s += (double)fabsf(w[i]);
    __shared__ double sm[256];
    sm[threadIdx.x] = s;
    __syncthreads();
    for (int off = 128; off > 0; off >>= 1) {
        if (threadIdx.x < off) sm[threadIdx.x] += sm[threadIdx.x + off];
        __syncthreads();
    }
    if (threadIdx.x == 0) g_partial[e*96 + chunk] = sm[0];
}

// ---------------- pass 2: finalize scales ------------------------------------
__global__ void finalize_kernel() {
    int e = threadIdx.x;
    if (e < NW) {
        double s = 0.0;
        for (int i = 0; i < 96; i++) s += g_partial[e*96 + i];
        g_scales[e] = (float)(s / (double)WELEM) + 1e-5f;
    }
}

// ---------------- pass 3: ternary quantize + rearrange [o][i][k]->[k][o][i] --
__global__ void quant_kernel(WPtrs wp) {
    int idx = blockIdx.x * 256 + threadIdx.x;
    if (idx >= NW * WELEM) return;
    int e = idx / WELEM;
    int r = idx - e * WELEM;
    int o = r / 1536;
    int rem = r - o * 1536;
    int i = rem / 3;
    int k = rem - i * 3;
    float sc = g_scales[e];
    float t = rintf(wp.p[e][r] / sc);       // round-half-even, matches jnp.round
    t = fminf(1.f, fmaxf(-1.f, t));
    g_wq[(size_t)e * WELEM + ((size_t)(k * C_ + o) * C_ + i)] = __float2half_rn(t);
}

// ---------------- transpose x[b][C][L] fp32 -> xT[b][L][C] fp16 ---------------
// 32 l x 64 c tiles; half2 stores give 128B/warp write transactions.
__global__ void tr_kernel(const float* __restrict__ x) {
    __shared__ __half t[64][33];   // [c][l]
    int b  = blockIdx.z;
    int l0 = blockIdx.x * 32, c0 = blockIdx.y * 64;
    int tx = threadIdx.x, ty = threadIdx.y;   // 32 x 8
    const float* xp = x + ((size_t)b * C_ + c0) * L_ + l0;
#pragma unroll
    for (int j = 0; j < 64; j += 8)
        t[ty + j][tx] = __float2half_rn(xp[(size_t)(ty + j) * L_ + tx]);
    __syncthreads();
    __half* xo = g_xt0 + ((size_t)b * L_ + l0) * C_ + c0;
#pragma unroll
    for (int r = 0; r < 4; r++) {
        int l = ty * 4 + r;                   // uniform per warp
        __half2 v;
        v.x = t[2 * tx    ][l];
        v.y = t[2 * tx + 1][l];
        *(__half2*)(xo + (size_t)l * C_ + 2 * tx) = v;
    }
}

// ---------------- fused conv (mma.sync fp16, ldmatrix + cp.async 2-buf) -------
// CTA tile: 128 o x 128 n, 2 CTAs/SM. K = 3 taps x 512 ic in 16 chunks of 32.
// Dynamic smem, rows padded to 40 halves (80B): ldmatrix phases conflict-free.
//   Ws: [buf][3][128][40]  at offset buf*30720          (2 x 30720 B)
//   Xs: [buf][144][40]     at offset 61440 + buf*11520  (2 x 11520 B)
// Total 84480 B dynamic. Only 128+2D X rows are filled (indices 8-D .. 135+D);
// compute reads exactly that span. Epilogue reuses smem as 128n x 136o fp16
// staging tile for fully-coalesced [L][C] fp16 stores.
// B operand: Xs stored [n][k] (k contiguous) -> NON-trans ldmatrix gives the
// exact m16n8k16 B fragment (thread i: Xs[n=i>>2][k=(i&3)*2 .. +1]).
// MODE 0: out_h[L][C] = fp16(leaky(scale*acc + bias))
// MODE 1: r = prev_f + scale*acc + bias -> out_f [C][L] fp32; opt out_h [L][C]
#define CONV_SMEM 84480
template<int D, int MODE>
__global__ __launch_bounds__(256, 2)
void conv_kernel(const __half* __restrict__ xin,        // [b][L][C] fp16
                 const __half* __restrict__ wq,         // [3][512][512] ternary fp16
                 const float* __restrict__ scale_p,
                 const float* __restrict__ bias,
                 const float* __restrict__ prev_f,
                 float* __restrict__ out_f,
                 __half* __restrict__ out_h,
                 int write_h)
{
    extern __shared__ char dsm[];
    const uint32_t sb = smem_u32(dsm);

    const int n0 = blockIdx.x * 128;
    const int o0 = blockIdx.y * 128;
    const int b  = blockIdx.z;
    const int tid  = threadIdx.x;
    const int lane = tid & 31;
    const int wid  = tid >> 5;
    const int oW = (wid & 3) * 32;   // warp o-offset
    const int nW = (wid >> 2) * 64;  // warp n-offset

    float acc[2][8][4];
#pragma unroll
    for (int a = 0; a < 2; a++)
#pragma unroll
        for (int c = 0; c < 8; c++)
#pragma unroll
            for (int j = 0; j < 4; j++) acc[a][c][j] = 0.f;

    const size_t bL = (size_t)b * L_;

    // stage fill: 1536 W chunks + (128+2D)*4 X chunks (rows 8-D .. 135+D)
    constexpr int NXR   = 128 + 2 * D;          // X rows actually used
    constexpr int NTOT  = 1536 + NXR * 4;       // total 16B chunks per stage
    constexpr int RO    = 8 - D;                // first filled row index
    auto fill = [&](int s, int buf) {
        int ic = s * 32;
        uint32_t wbase = sb + buf * 30720;
        uint32_t xbase = sb + 61440 + buf * 11520;
#pragma unroll
        for (int i = 0; i < 9; i++) {
            int c = tid + i * 256;
            if (c < 1536) {                       // weights
                int row = c >> 2, q = c & 3;
                int t = row >> 7, o = row & 127;
                const __half* src = wq + ((size_t)(t * C_ + o0 + o)) * C_ + ic + q * 8;
                cpa16(wbase + (uint32_t)(((t * 128 + o) * 40 + q * 8) * 2), src, 16);
            } else if (c < NTOT) {                // activations
                int c2 = c - 1536;
                int r = c2 >> 2, q = c2 & 3;      // r = 0..NXR-1, row idx = r+RO
                int l = n0 - D + r;
                int lc = l < 0 ? 0 : (l >= L_ ? L_ - 1 : l);
                uint32_t sz = (l >= 0 && l < L_) ? 16u : 0u;
                const __half* src = xin + (bL + lc) * C_ + ic + q * 8;
                cpa16(xbase + (uint32_t)(((r + RO) * 40 + q * 8) * 2), src, sz);
            }
        }
        asm volatile("cp.async.commit_group;" ::: "memory");
    };

    // per-lane ldmatrix address components
    const uint32_t aRow  = lane & 15;                 // A: row within 16
    const uint32_t aColH = (lane >> 4) * 8;           // A: k-half select
    const uint32_t bR    = lane & 7;                  // B: n-row within 8x8 tile
    const uint32_t bNH   = ((lane >> 4) & 1) * 8;     // B: n-tile select (matrices 2,3)
    const uint32_t bKH   = ((lane >> 3) & 1) * 8;     // B: k-half select (matrices 1,3)

    fill(0, 0);
    for (int s = 0; s < 16; s++) {
        const int buf = s & 1;
        asm volatile("cp.async.wait_group 0;" ::: "memory");
        __syncthreads();
        if (s + 1 < 16) fill(s + 1, buf ^ 1);

        const uint32_t wbase = sb + buf * 30720;
        const uint32_t xbase = sb + 61440 + buf * 11520;

#pragma unroll
        for (int t = 0; t < 3; t++) {
            const int shift = (8 - D) + t * D;
            const uint32_t nrow = nW + bNH + bR + shift;
#pragma unroll
            for (int kg = 0; kg < 2; kg++) {
                uint32_t a0,a1,a2,a3, a4,a5,a6,a7;
                uint32_t aa = wbase + ((t * 128 + oW + aRow) * 40 + kg * 16 + aColH) * 2;
                LDSM_X4(a0,a1,a2,a3, aa);
                LDSM_X4(a4,a5,a6,a7, aa + 16 * 80);
#pragma unroll
                for (int nia = 0; nia < 4; nia++) {
                    uint32_t b0,b1,b2,b3;
                    uint32_t ba = xbase + ((nrow + nia * 16) * 40 + kg * 16 + bKH) * 2;
                    LDSM_X4(b0,b1,b2,b3, ba);     // non-trans: [n][k] rows ARE B frags
                    MMA16816(acc[0][2*nia    ], a0,a1,a2,a3, b0,b1);
                    MMA16816(acc[0][2*nia + 1], a0,a1,a2,a3, b2,b3);
                    MMA16816(acc[1][2*nia    ], a4,a5,a6,a7, b0,b1);
                    MMA16816(acc[1][2*nia + 1], a4,a5,a6,a7, b2,b3);
                }
            }
        }
    }

    const float scale = *scale_p;
    const bool stage_h = (MODE == 0) || (write_h != 0);
    __half* ho = (__half*)dsm;               // 128 rows x 136 halves (272 B/row)

    if (stage_h) __syncthreads();            // all K-loop smem readers done

#pragma unroll
    for (int mi = 0; mi < 2; mi++) {
#pragma unroll
        for (int half = 0; half < 2; half++) {
            int ol = oW + mi*16 + (lane >> 2) + half*8;   // 0..127
            int o  = o0 + ol;
            float bv = bias[o];
#pragma unroll
            for (int ni = 0; ni < 8; ni++) {
                int cl = nW + ni*8 + (lane & 3)*2;        // 0..127
                float v0 = acc[mi][ni][half*2 + 0] * scale + bv;
                float v1 = acc[mi][ni][half*2 + 1] * scale + bv;
                if (MODE == 0) {
                    v0 = v0 >= 0.f ? v0 : 0.1f * v0;
                    v1 = v1 >= 0.f ? v1 : 0.1f * v1;
                    ho[(cl    ) * 136 + ol] = __float2half_rn(v0);
                    ho[(cl + 1) * 136 + ol] = __float2half_rn(v1);
                } else {
                    size_t gi = ((size_t)b * C_ + o) * L_ + n0 + cl;
                    float2 pv = *((const float2*)(prev_f + gi));
                    float r0 = pv.x + v0, r1 = pv.y + v1;
                    *((float2*)(out_f + gi)) = make_float2(r0, r1);
                    if (write_h) {
                        ho[(cl    ) * 136 + ol] = __float2half_rn(r0);
                        ho[(cl + 1) * 136 + ol] = __float2half_rn(r1);
                    }
                }
            }
        }
    }

    if (stage_h) {
        __syncthreads();
        // cooperative coalesced write: 128 rows x 256 B
#pragma unroll
        for (int i = 0; i < 8; i++) {
            int idx = i * 256 + tid;          // 0..2047
            int row = idx >> 4, seg = idx & 15;
            uint4 v = *(const uint4*)(dsm + row * 272 + seg * 16);
            *(uint4*)(out_h + (bL + n0 + row) * C_ + o0 + seg * 8) = v;
        }
    }
}

// ---------------- launch ------------------------------------------------------
extern "C" void kernel_launch(void* const* d_in, const int* in_sizes, int n_in,
                              void* d_out, int out_size)
{
    (void)in_sizes; (void)n_in; (void)out_size;
    const float* x = (const float*)d_in[0];
    WPtrs wp;
    const float* biasA[3];
    const float* biasB[3];
    for (int br = 0; br < 3; br++) {
        wp.p[2*br + 0] = (const float*)d_in[1 + 4*br];   // wA
        biasA[br]      = (const float*)d_in[2 + 4*br];   // bA
        wp.p[2*br + 1] = (const float*)d_in[3 + 4*br];   // wB
        biasB[br]      = (const float*)d_in[4 + 4*br];   // bB
    }

    void *p_wq, *p_x0, *p_x1, *p_y, *p_f0, *p_f1, *p_sc;
    cudaGetSymbolAddress(&p_wq, g_wq);
    cudaGetSymbolAddress(&p_x0, g_xt0);
    cudaGetSymbolAddress(&p_x1, g_xt1);
    cudaGetSymbolAddress(&p_y,  g_yt);
    cudaGetSymbolAddress(&p_f0, g_xf0);
    cudaGetSymbolAddress(&p_f1, g_xf1);
    cudaGetSymbolAddress(&p_sc, g_scales);
    __half* wq  = (__half*)p_wq;
    __half* xt0 = (__half*)p_x0;
    __half* xt1 = (__half*)p_x1;
    __half* yt  = (__half*)p_y;
    float* xf0 = (float*)p_f0;
    float* xf1 = (float*)p_f1;
    float* scales = (float*)p_sc;

    cudaFuncSetAttribute(conv_kernel<1,0>, cudaFuncAttributeMaxDynamicSharedMemorySize, CONV_SMEM);
    cudaFuncSetAttribute(conv_kernel<1,1>, cudaFuncAttributeMaxDynamicSharedMemorySize, CONV_SMEM);
    cudaFuncSetAttribute(conv_kernel<3,0>, cudaFuncAttributeMaxDynamicSharedMemorySize, CONV_SMEM);
    cudaFuncSetAttribute(conv_kernel<5,0>, cudaFuncAttributeMaxDynamicSharedMemorySize, CONV_SMEM);

    dim3 rg(96, NW);
    wabs_kernel<<<rg, 256>>>(wp);
    finalize_kernel<<<1, 32>>>();
    quant_kernel<<<(NW * WELEM + 255) / 256, 256>>>(wp);
    dim3 tg(L_ / 32, C_ / 64, B_);
    tr_kernel<<<tg, dim3(32, 8)>>>(x);

    dim3 cg(L_ / 128, C_ / 128, B_);   // 64 x 4 x 8 = 2048 CTAs
    // branch 0: dilation 1
    conv_kernel<1, 0><<<cg, 256, CONV_SMEM>>>(xt0, wq + 0*(size_t)WELEM, scales + 0, biasA[0],
                                              nullptr, nullptr, yt, 0);
    conv_kernel<1, 1><<<cg, 256, CONV_SMEM>>>(yt,  wq + 1*(size_t)WELEM, scales + 1, biasB[0],
                                              x, xf0, xt1, 1);
    // branch 1: dilation 3
    conv_kernel<3, 0><<<cg, 256, CONV_SMEM>>>(xt1, wq + 2*(size_t)WELEM, scales + 2, biasA[1],
                                              nullptr, nullptr, yt, 0);
    conv_kernel<1, 1><<<cg, 256, CONV_SMEM>>>(yt,  wq + 3*(size_t)WELEM, scales + 3, biasB[1],
                                              xf0, xf1, xt0, 1);
    // branch 2: dilation 5
    conv_kernel<5, 0><<<cg, 256, CONV_SMEM>>>(xt0, wq + 4*(size_t)WELEM, scales + 4, biasA[2],
                                              nullptr, nullptr, yt, 0);
    conv_kernel<1, 1><<<cg, 256, CONV_SMEM>>>(yt,  wq + 5*(size_t)WELEM, scales + 5, biasB[2],
                                              xf1, (float*)d_out, nullptr, 0);
}